// round 12
// baseline (speedup 1.0000x reference)
#include <cuda_runtime.h>
#include <math.h>

// ----------------------------------------------------------------------------
// Problem constants (fixed shapes)
// ----------------------------------------------------------------------------
#define T_STEPS 4096
#define INP_DIM 512
#define HID     1024
#define GATES   4096   // 4*HID

// Recurrent kernel config
#define NCTA      128           // CTAs; each owns 8 hidden columns
#define COLS      8             // columns per CTA
#define NTHREADS  256           // 8 warps; warp w owns column j0+w

// SMEM layout (floats):
#define SW1_F     (2 * 8 * 1024)
#define SCR_F     (8 * 1024)
#define SMEM_FLOATS (SW1_F + SCR_F + 1024 + 1024)
#define SMEM_BYTES  (SMEM_FLOATS * 4)

// Poll pacing (dependent-FMA units; ~4 cyc each). LTS has headroom at NAT
// clock, so poll tighter than R6 to shrink detect granularity.
#define PACE_FIRST  16   // ~64 cyc first backoff
#define PACE_STEADY 32   // ~128 cyc steady-state

// ----------------------------------------------------------------------------
// Device scratch (allocation-free: __device__ globals)
// ----------------------------------------------------------------------------
__device__ float g_xp[(size_t)T_STEPS * GATES];           // 64 MB: x @ W_xg
__device__ unsigned long long g_cpack[HID];               // (tag<<32)|c bits
__device__ unsigned long long g_hpack[HID];               // (tag<<32)|h bits

// ----------------------------------------------------------------------------
// Kernel 1: x_proj = x @ W_xg   (fp32 SGEMM, 128x128 tile, BK=16, 8x8/thread)
// ----------------------------------------------------------------------------
#define BSP 132   // padded SMEM row

__global__ void __launch_bounds__(256)
sgemm_xproj(const float* __restrict__ A,   // x      [4096, 512]
            const float* __restrict__ B)   // W_xg   [512, 4096]
{
    __shared__ float As[16 * BSP];
    __shared__ float Bs[16 * BSP];

    const int tid = threadIdx.x;
    const int bm  = blockIdx.y;
    const int bn  = blockIdx.x;
    const int ty  = tid >> 4;
    const int tx  = tid & 15;

    float acc[8][8];
#pragma unroll
    for (int i = 0; i < 8; i++)
#pragma unroll
        for (int j = 0; j < 8; j++) acc[i][j] = 0.f;

    for (int kt = 0; kt < INP_DIM / 16; kt++) {
#pragma unroll
        for (int s = 0; s < 2; s++) {
            int f   = tid + s * 256;
            int row = f >> 2;
            int kq  = f & 3;
            float4 av = *(const float4*)(A + (size_t)(bm * 128 + row) * INP_DIM
                                           + kt * 16 + kq * 4);
            As[(kq * 4 + 0) * BSP + row] = av.x;
            As[(kq * 4 + 1) * BSP + row] = av.y;
            As[(kq * 4 + 2) * BSP + row] = av.z;
            As[(kq * 4 + 3) * BSP + row] = av.w;
        }
#pragma unroll
        for (int s = 0; s < 2; s++) {
            int f  = tid + s * 256;
            int kk = f >> 5;
            int cq = f & 31;
            float4 bv = *(const float4*)(B + (size_t)(kt * 16 + kk) * GATES
                                           + bn * 128 + cq * 4);
            *(float4*)(&Bs[kk * BSP + cq * 4]) = bv;
        }
        __syncthreads();

#pragma unroll
        for (int kk = 0; kk < 16; kk++) {
            float4 a0 = *(const float4*)(&As[kk * BSP + ty * 8]);
            float4 a1 = *(const float4*)(&As[kk * BSP + ty * 8 + 4]);
            float4 b0 = *(const float4*)(&Bs[kk * BSP + tx * 8]);
            float4 b1 = *(const float4*)(&Bs[kk * BSP + tx * 8 + 4]);
            float ar[8] = {a0.x, a0.y, a0.z, a0.w, a1.x, a1.y, a1.z, a1.w};
            float br[8] = {b0.x, b0.y, b0.z, b0.w, b1.x, b1.y, b1.z, b1.w};
#pragma unroll
            for (int i = 0; i < 8; i++)
#pragma unroll
                for (int j = 0; j < 8; j++) acc[i][j] += ar[i] * br[j];
        }
        __syncthreads();
    }

#pragma unroll
    for (int i = 0; i < 8; i++) {
        size_t base = (size_t)(bm * 128 + ty * 8 + i) * GATES + bn * 128 + tx * 8;
        *(float4*)(&g_xp[base])     = make_float4(acc[i][0], acc[i][1], acc[i][2], acc[i][3]);
        *(float4*)(&g_xp[base + 4]) = make_float4(acc[i][4], acc[i][5], acc[i][6], acc[i][7]);
    }
}

// ----------------------------------------------------------------------------
// Fast pointwise (fp32, ~1e-6 rel err)
// ----------------------------------------------------------------------------
__device__ __forceinline__ float fsigmoid(float x) {
    return 1.0f / (1.0f + __expf(-x));
}
__device__ __forceinline__ float ftanh(float x) {
    return 1.0f - 2.0f / (__expf(2.0f * x) + 1.0f);
}

// ----------------------------------------------------------------------------
// Tag-stamped broadcast (fused detection+data: the detecting load IS the data
// load). Producer: one volatile 8B store of (tag<<32)|bits.
// Consumer: thread tid polls 4 contiguous words (one 32B sector) with two
// concurrent v2.u64 volatile loads; failed rounds pace with dependent FMAs.
// ----------------------------------------------------------------------------
__device__ __forceinline__ void publish(unsigned long long* arr, int j,
                                        unsigned tag, float v) {
    unsigned long long p = ((unsigned long long)tag << 32) |
                           (unsigned long long)__float_as_uint(v);
    *((volatile unsigned long long*)(arr + j)) = p;
}

__device__ __forceinline__ void pace_fmas(int n, float* sink) {
    float s = *sink;
    for (int i = 0; i < n; i++)
        asm volatile("fma.rn.f32 %0, %0, %1, %2;"
                     : "+f"(s) : "f"(0.5f), "f"(0.25f));
    *sink = s;
}

// Gathers into dst (smem) AND returns this thread's 4 values
// (used for the coalesced `out` store on the h-exchange).
__device__ __forceinline__ float4 poll_gather4(const unsigned long long* arr,
                                               unsigned tag, float* dst, int tid,
                                               float* sink) {
    const unsigned long long* p = arr + 4 * tid;
    unsigned long long a0 = 0, a1 = 0, b0 = 0, b1 = 0;
    bool gotA = false, gotB = false;
    int pace = PACE_FIRST;
    for (;;) {
        if (!gotA) {
            asm volatile("ld.volatile.global.v2.u64 {%0,%1},[%2];"
                         : "=l"(a0), "=l"(a1) : "l"(p) : "memory");
        }
        if (!gotB) {
            asm volatile("ld.volatile.global.v2.u64 {%0,%1},[%2];"
                         : "=l"(b0), "=l"(b1) : "l"(p + 2) : "memory");
        }
        gotA = gotA || (((unsigned)(a0 >> 32) == tag) && ((unsigned)(a1 >> 32) == tag));
        gotB = gotB || (((unsigned)(b0 >> 32) == tag) && ((unsigned)(b1 >> 32) == tag));
        if (gotA && gotB) break;
        pace_fmas(pace, sink);
        pace = PACE_STEADY;
    }
    float4 v = make_float4(__uint_as_float((unsigned)a0),
                           __uint_as_float((unsigned)a1),
                           __uint_as_float((unsigned)b0),
                           __uint_as_float((unsigned)b1));
    *(float4*)(dst + 4 * tid) = v;
    return v;
}

// ----------------------------------------------------------------------------
// Kernel 2: persistent recurrence. 128 CTAs x 256 threads; warp w owns
// column j = 8*blockIdx.x + w.
// Register-resident: gates o,f,i (W_hg cols) and W_cr column.
// SMEM-resident:     gate g and W_hr column.
// x_proj inputs for step t+1 prefetched during step t.
// ----------------------------------------------------------------------------
__global__ void __launch_bounds__(NTHREADS, 1)
lstm_recur(const float* __restrict__ W_hg,   // [1024, 4096]
           const float* __restrict__ W_hr,   // [1024, 1024]
           const float* __restrict__ W_cr,   // [1024, 1024]
           const float* __restrict__ b_g,    // [4096]
           const float* __restrict__ b_r,    // [1024]
           float* __restrict__ out)          // [4096, 1024]
{
    extern __shared__ float smem[];
    float* sW1     = smem;                    // 2*8*1024 (slot0: g-gate, slot1: W_hr)
    float* scratch = smem + SW1_F;            // 8*1024
    float* sc      = smem + SW1_F + SCR_F;    // 1024
    float* sh      = sc + 1024;               // 1024

    const int tid  = threadIdx.x;
    const int w    = tid >> 5;
    const int lane = tid & 31;
    const int j0   = blockIdx.x * COLS;
    const int j    = j0 + w;

    // ---- Stage SMEM-resident weights (coalesced) ----
    for (int idx = tid; idx < COLS * 1024; idx += NTHREADS) {
        int cl = idx & 7;
        int k  = idx >> 3;
        sW1[(size_t)(0 * 8 + cl) * 1024 + k] = W_hg[(size_t)k * GATES + 3 * HID + j0 + cl];
        sW1[(size_t)(1 * 8 + cl) * 1024 + k] = W_hr[(size_t)k * HID + j0 + cl];
    }

    // ---- Stage register weights via scratch ----
    // Contract: hreg[q].{x..w} = h[128q + 4*lane + d]
    float4 wo[8], wf[8], wi[8], wcr[8];
    const float4* scrv = (const float4*)scratch;
#pragma unroll
    for (int g = 0; g < 4; g++) {
        __syncthreads();
        for (int idx = tid; idx < COLS * 1024; idx += NTHREADS) {
            int cl = idx & 7;
            int k  = idx >> 3;
            float v;
            if (g < 3) v = W_hg[(size_t)k * GATES + g * HID + j0 + cl];
            else       v = W_cr[(size_t)k * HID + j0 + cl];
            scratch[(size_t)cl * 1024 + k] = v;
        }
        __syncthreads();
#pragma unroll
        for (int q = 0; q < 8; q++) {
            float4 v = scrv[w * 256 + 32 * q + lane];
            if (g == 0) wo[q] = v;
            else if (g == 1) wf[q] = v;
            else if (g == 2) wi[q] = v;
            else wcr[q] = v;
        }
    }
    __syncthreads();

    // Lane-0 constants
    float bg0 = 0.f, bg1 = 0.f, bg2 = 0.f, bg3 = 0.f, brj = 0.f;
    if (lane == 0) {
        bg0 = b_g[j];
        bg1 = b_g[HID + j];
        bg2 = b_g[2 * HID + j];
        bg3 = b_g[3 * HID + j];
        brj = b_r[j];
    }

    float c_state = 0.f;
    float4 hreg[8];
#pragma unroll
    for (int q = 0; q < 8; q++) hreg[q] = make_float4(0.f, 0.f, 0.f, 0.f);

    const float4* w1v = (const float4*)sW1;
    const float4* scv = (const float4*)sc;
    const float4* shv = (const float4*)sh;

    float sink = 1.5f;

    // ---- Prime x_proj pipeline for t=0 ----
    float xpo = 0.f, xpf = 0.f, xpi = 0.f, xpg = 0.f;
    if (lane == 0) {
        xpf = __ldg(g_xp + HID + j);
        xpi = __ldg(g_xp + 2 * HID + j);
        xpg = __ldg(g_xp + 3 * HID + j);
        xpo = __ldg(g_xp + j);
    }

    for (int t = 0; t < T_STEPS; t++) {
        const unsigned tag = (unsigned)(t + 1);

        // ---- Phase 1a (critical): f, i, g dots -> publish c ----
        float af = 0.f, ai = 0.f, ag = 0.f;
        const float4* wpg = w1v + (size_t)(0 * 8 + w) * 256;
#pragma unroll
        for (int q = 0; q < 8; q++) {
            float4 hv = hreg[q];
            float4 vf = wf[q], vi = wi[q];
            af += vf.x * hv.x + vf.y * hv.y + vf.z * hv.z + vf.w * hv.w;
            ai += vi.x * hv.x + vi.y * hv.y + vi.z * hv.z + vi.w * hv.w;
            float4 vg = wpg[lane + 32 * q];
            ag += vg.x * hv.x + vg.y * hv.y + vg.z * hv.z + vg.w * hv.w;
        }
#pragma unroll
        for (int off = 16; off; off >>= 1) {
            af += __shfl_xor_sync(0xffffffffu, af, off);
            ai += __shfl_xor_sync(0xffffffffu, ai, off);
            ag += __shfl_xor_sync(0xffffffffu, ag, off);
        }
        if (lane == 0) {
            float f_t = fsigmoid(af + xpf + bg1);
            float i_t = fsigmoid(ai + xpi + bg2);
            c_state = f_t * c_state + i_t * ftanh(ag + xpg + bg3);
            publish(g_cpack, j, tag, c_state);   // barrier-1 + data, fused
        }

        // ---- Phase 1b (overlapped with c-exchange): o and W_hr dots ----
        float ao = 0.f, ar = 0.f;
        const float4* wpr = w1v + (size_t)(1 * 8 + w) * 256;
#pragma unroll
        for (int q = 0; q < 8; q++) {
            float4 hv = hreg[q];
            float4 vo = wo[q];
            ao += vo.x * hv.x + vo.y * hv.y + vo.z * hv.z + vo.w * hv.w;
            float4 vr = wpr[lane + 32 * q];
            ar += vr.x * hv.x + vr.y * hv.y + vr.z * hv.z + vr.w * hv.w;
        }
#pragma unroll
        for (int off = 16; off; off >>= 1) {
            ao += __shfl_xor_sync(0xffffffffu, ao, off);
            ar += __shfl_xor_sync(0xffffffffu, ar, off);
        }
        float o_val = 0.f, r1 = 0.f;
        if (lane == 0) {
            o_val = fsigmoid(ao + xpo + bg0);
            r1 = ar;
            // Prefetch x_proj for step t+1 (hidden behind the exchanges)
            if (t + 1 < T_STEPS) {
                const float* xpn = g_xp + (size_t)(t + 1) * GATES;
                xpf = __ldg(xpn + HID + j);
                xpi = __ldg(xpn + 2 * HID + j);
                xpg = __ldg(xpn + 3 * HID + j);
                xpo = __ldg(xpn + j);
            }
        }

        // ---- Gather c_t (grid barrier + data) ----
        poll_gather4(g_cpack, tag, sc, tid, &sink);
        __syncthreads();

        // ---- Phase 2: r2 = c_t . W_cr[:,j] ----
        float a2 = 0.f;
#pragma unroll
        for (int q = 0; q < 8; q++) {
            float4 cv = scv[lane + 32 * q];
            float4 wv = wcr[q];
            a2 += wv.x * cv.x + wv.y * cv.y + wv.z * cv.z + wv.w * cv.w;
        }
#pragma unroll
        for (int off = 16; off; off >>= 1)
            a2 += __shfl_xor_sync(0xffffffffu, a2, off);

        if (lane == 0) {
            float hn = o_val * ftanh(r1 + a2 + brj);
            publish(g_hpack, j, tag, hn);        // publish (critical)
        }

        // ---- Gather h_t; write out coalesced from gathered registers ----
        float4 hv4 = poll_gather4(g_hpack, tag, sh, tid, &sink);
        *(float4*)(out + (size_t)t * HID + 4 * tid) = hv4;
        __syncthreads();
#pragma unroll
        for (int q = 0; q < 8; q++)
            hreg[q] = shv[lane + 32 * q];
    }

    // Prevent sink elimination (never true)
    if (sink == 12345.678f && tid == 9999) out[0] = sink;
}

// ----------------------------------------------------------------------------
// Launch
// ----------------------------------------------------------------------------
extern "C" void kernel_launch(void* const* d_in, const int* in_sizes, int n_in,
                              void* d_out, int out_size) {
    const float* x    = (const float*)d_in[0];   // [4096, 512]
    const float* W_xg = (const float*)d_in[1];   // [512, 4096]
    const float* W_hg = (const float*)d_in[2];   // [1024, 4096]
    const float* b_g  = (const float*)d_in[3];   // [1, 4096]
    const float* W_cr = (const float*)d_in[4];   // [1024, 1024]
    const float* W_hr = (const float*)d_in[5];   // [1024, 1024]
    const float* b_r  = (const float*)d_in[6];   // [1, 1024]
    float* out = (float*)d_out;                  // [4096, 1, 1024]

    (void)in_sizes; (void)n_in; (void)out_size;

    dim3 ggrid(GATES / 128, T_STEPS / 128);
    sgemm_xproj<<<ggrid, 256>>>(x, W_xg);

    cudaFuncSetAttribute(lstm_recur, cudaFuncAttributeMaxDynamicSharedMemorySize,
                         SMEM_BYTES);
    lstm_recur<<<NCTA, NTHREADS, SMEM_BYTES>>>(W_hg, W_hr, W_cr, b_g, b_r, out);
}

// round 13
// speedup vs baseline: 1.0042x; 1.0042x over previous
#include <cuda_runtime.h>
#include <math.h>

// ----------------------------------------------------------------------------
// Problem constants (fixed shapes)
// ----------------------------------------------------------------------------
#define T_STEPS 4096
#define INP_DIM 512
#define HID     1024
#define GATES   4096   // 4*HID

// Recurrent kernel config
#define NCTA      128           // CTAs; each owns 8 hidden columns
#define COLS      8             // columns per CTA
#define NTHREADS  256           // 8 warps; warp w owns column j0+w

// SMEM layout (floats):
#define SW1_F     (2 * 8 * 1024)
#define SCR_F     (8 * 1024)
#define SMEM_FLOATS (SW1_F + SCR_F + 1024 + 1024)
#define SMEM_BYTES  (SMEM_FLOATS * 4)

// Poll pacing (dependent-FMA units; ~4 cyc each).
// KEY CHANGE: ~400 cyc/round keeps aggregate spin traffic at ~50% of the
// LTS cap (32768 thr x 32B / 400cyc ~ 4.5 TB/s < 8.4 TB/s measured ceiling),
// decongesting the critical publish->visible and gather round-trips that
// have been queueing behind saturated poll traffic in every prior variant.
#define PACE_STEADY 100

// ----------------------------------------------------------------------------
// Device scratch (allocation-free: __device__ globals)
// ----------------------------------------------------------------------------
__device__ float g_xp[(size_t)T_STEPS * GATES];           // 64 MB: x @ W_xg
__device__ unsigned long long g_cpack[HID];               // (tag<<32)|c bits
__device__ unsigned long long g_hpack[HID];               // (tag<<32)|h bits

// ----------------------------------------------------------------------------
// Kernel 1: x_proj = x @ W_xg   (fp32 SGEMM, 128x128 tile, BK=16, 8x8/thread)
// ----------------------------------------------------------------------------
#define BSP 132   // padded SMEM row

__global__ void __launch_bounds__(256)
sgemm_xproj(const float* __restrict__ A,   // x      [4096, 512]
            const float* __restrict__ B)   // W_xg   [512, 4096]
{
    __shared__ float As[16 * BSP];
    __shared__ float Bs[16 * BSP];

    const int tid = threadIdx.x;
    const int bm  = blockIdx.y;
    const int bn  = blockIdx.x;
    const int ty  = tid >> 4;
    const int tx  = tid & 15;

    float acc[8][8];
#pragma unroll
    for (int i = 0; i < 8; i++)
#pragma unroll
        for (int j = 0; j < 8; j++) acc[i][j] = 0.f;

    for (int kt = 0; kt < INP_DIM / 16; kt++) {
#pragma unroll
        for (int s = 0; s < 2; s++) {
            int f   = tid + s * 256;
            int row = f >> 2;
            int kq  = f & 3;
            float4 av = *(const float4*)(A + (size_t)(bm * 128 + row) * INP_DIM
                                           + kt * 16 + kq * 4);
            As[(kq * 4 + 0) * BSP + row] = av.x;
            As[(kq * 4 + 1) * BSP + row] = av.y;
            As[(kq * 4 + 2) * BSP + row] = av.z;
            As[(kq * 4 + 3) * BSP + row] = av.w;
        }
#pragma unroll
        for (int s = 0; s < 2; s++) {
            int f  = tid + s * 256;
            int kk = f >> 5;
            int cq = f & 31;
            float4 bv = *(const float4*)(B + (size_t)(kt * 16 + kk) * GATES
                                           + bn * 128 + cq * 4);
            *(float4*)(&Bs[kk * BSP + cq * 4]) = bv;
        }
        __syncthreads();

#pragma unroll
        for (int kk = 0; kk < 16; kk++) {
            float4 a0 = *(const float4*)(&As[kk * BSP + ty * 8]);
            float4 a1 = *(const float4*)(&As[kk * BSP + ty * 8 + 4]);
            float4 b0 = *(const float4*)(&Bs[kk * BSP + tx * 8]);
            float4 b1 = *(const float4*)(&Bs[kk * BSP + tx * 8 + 4]);
            float ar[8] = {a0.x, a0.y, a0.z, a0.w, a1.x, a1.y, a1.z, a1.w};
            float br[8] = {b0.x, b0.y, b0.z, b0.w, b1.x, b1.y, b1.z, b1.w};
#pragma unroll
            for (int i = 0; i < 8; i++)
#pragma unroll
                for (int j = 0; j < 8; j++) acc[i][j] += ar[i] * br[j];
        }
        __syncthreads();
    }

#pragma unroll
    for (int i = 0; i < 8; i++) {
        size_t base = (size_t)(bm * 128 + ty * 8 + i) * GATES + bn * 128 + tx * 8;
        *(float4*)(&g_xp[base])     = make_float4(acc[i][0], acc[i][1], acc[i][2], acc[i][3]);
        *(float4*)(&g_xp[base + 4]) = make_float4(acc[i][4], acc[i][5], acc[i][6], acc[i][7]);
    }
}

// ----------------------------------------------------------------------------
// Fast pointwise (fp32, ~1e-6 rel err)
// ----------------------------------------------------------------------------
__device__ __forceinline__ float fsigmoid(float x) {
    return 1.0f / (1.0f + __expf(-x));
}
__device__ __forceinline__ float ftanh(float x) {
    return 1.0f - 2.0f / (__expf(2.0f * x) + 1.0f);
}

// ----------------------------------------------------------------------------
// Tag-stamped broadcast (fused detection+data: the detecting load IS the data
// load). Producer: one volatile 8B store of (tag<<32)|bits.
// Consumer: thread tid polls 4 contiguous words (one 32B sector) with two
// concurrent v2.u64 volatile loads; failed rounds pace ~400 cyc (+ per-warp
// jitter to desmear bursts), keeping spin traffic at ~half the LTS cap.
// ----------------------------------------------------------------------------
__device__ __forceinline__ void publish(unsigned long long* arr, int j,
                                        unsigned tag, float v) {
    unsigned long long p = ((unsigned long long)tag << 32) |
                           (unsigned long long)__float_as_uint(v);
    *((volatile unsigned long long*)(arr + j)) = p;
}

__device__ __forceinline__ void pace_fmas(int n, float* sink) {
    float s = *sink;
    for (int i = 0; i < n; i++)
        asm volatile("fma.rn.f32 %0, %0, %1, %2;"
                     : "+f"(s) : "f"(0.5f), "f"(0.25f));
    *sink = s;
}

// Gathers into dst (smem) AND returns this thread's 4 values
// (used for the coalesced `out` store on the h-exchange).
__device__ __forceinline__ float4 poll_gather4(const unsigned long long* arr,
                                               unsigned tag, float* dst, int tid,
                                               int pace, float* sink) {
    const unsigned long long* p = arr + 4 * tid;
    unsigned long long a0 = 0, a1 = 0, b0 = 0, b1 = 0;
    bool gotA = false, gotB = false;
    for (;;) {
        if (!gotA) {
            asm volatile("ld.volatile.global.v2.u64 {%0,%1},[%2];"
                         : "=l"(a0), "=l"(a1) : "l"(p) : "memory");
        }
        if (!gotB) {
            asm volatile("ld.volatile.global.v2.u64 {%0,%1},[%2];"
                         : "=l"(b0), "=l"(b1) : "l"(p + 2) : "memory");
        }
        gotA = gotA || (((unsigned)(a0 >> 32) == tag) && ((unsigned)(a1 >> 32) == tag));
        gotB = gotB || (((unsigned)(b0 >> 32) == tag) && ((unsigned)(b1 >> 32) == tag));
        if (gotA && gotB) break;
        pace_fmas(pace, sink);
    }
    float4 v = make_float4(__uint_as_float((unsigned)a0),
                           __uint_as_float((unsigned)a1),
                           __uint_as_float((unsigned)b0),
                           __uint_as_float((unsigned)b1));
    *(float4*)(dst + 4 * tid) = v;
    return v;
}

// ----------------------------------------------------------------------------
// Kernel 2: persistent recurrence. 128 CTAs x 256 threads; warp w owns
// column j = 8*blockIdx.x + w.
// Register-resident: gates o,f,i (W_hg cols) and W_cr column.
// SMEM-resident:     gate g and W_hr column.
// x_proj inputs for step t+1 prefetched during step t.
// ----------------------------------------------------------------------------
__global__ void __launch_bounds__(NTHREADS, 1)
lstm_recur(const float* __restrict__ W_hg,   // [1024, 4096]
           const float* __restrict__ W_hr,   // [1024, 1024]
           const float* __restrict__ W_cr,   // [1024, 1024]
           const float* __restrict__ b_g,    // [4096]
           const float* __restrict__ b_r,    // [1024]
           float* __restrict__ out)          // [4096, 1024]
{
    extern __shared__ float smem[];
    float* sW1     = smem;                    // 2*8*1024 (slot0: g-gate, slot1: W_hr)
    float* scratch = smem + SW1_F;            // 8*1024
    float* sc      = smem + SW1_F + SCR_F;    // 1024
    float* sh      = sc + 1024;               // 1024

    const int tid  = threadIdx.x;
    const int w    = tid >> 5;
    const int lane = tid & 31;
    const int j0   = blockIdx.x * COLS;
    const int j    = j0 + w;

    // Per-warp pace jitter (warp-uniform to avoid intra-warp divergence):
    // spreads poll rounds across ~0-224 extra cycles to smooth traffic bursts.
    const int pace = PACE_STEADY + (w << 3);

    // ---- Stage SMEM-resident weights (coalesced) ----
    for (int idx = tid; idx < COLS * 1024; idx += NTHREADS) {
        int cl = idx & 7;
        int k  = idx >> 3;
        sW1[(size_t)(0 * 8 + cl) * 1024 + k] = W_hg[(size_t)k * GATES + 3 * HID + j0 + cl];
        sW1[(size_t)(1 * 8 + cl) * 1024 + k] = W_hr[(size_t)k * HID + j0 + cl];
    }

    // ---- Stage register weights via scratch ----
    // Contract: hreg[q].{x..w} = h[128q + 4*lane + d]
    float4 wo[8], wf[8], wi[8], wcr[8];
    const float4* scrv = (const float4*)scratch;
#pragma unroll
    for (int g = 0; g < 4; g++) {
        __syncthreads();
        for (int idx = tid; idx < COLS * 1024; idx += NTHREADS) {
            int cl = idx & 7;
            int k  = idx >> 3;
            float v;
            if (g < 3) v = W_hg[(size_t)k * GATES + g * HID + j0 + cl];
            else       v = W_cr[(size_t)k * HID + j0 + cl];
            scratch[(size_t)cl * 1024 + k] = v;
        }
        __syncthreads();
#pragma unroll
        for (int q = 0; q < 8; q++) {
            float4 v = scrv[w * 256 + 32 * q + lane];
            if (g == 0) wo[q] = v;
            else if (g == 1) wf[q] = v;
            else if (g == 2) wi[q] = v;
            else wcr[q] = v;
        }
    }
    __syncthreads();

    // Lane-0 constants
    float bg0 = 0.f, bg1 = 0.f, bg2 = 0.f, bg3 = 0.f, brj = 0.f;
    if (lane == 0) {
        bg0 = b_g[j];
        bg1 = b_g[HID + j];
        bg2 = b_g[2 * HID + j];
        bg3 = b_g[3 * HID + j];
        brj = b_r[j];
    }

    float c_state = 0.f;
    float4 hreg[8];
#pragma unroll
    for (int q = 0; q < 8; q++) hreg[q] = make_float4(0.f, 0.f, 0.f, 0.f);

    const float4* w1v = (const float4*)sW1;
    const float4* scv = (const float4*)sc;
    const float4* shv = (const float4*)sh;

    float sink = 1.5f;

    // ---- Prime x_proj pipeline for t=0 ----
    float xpo = 0.f, xpf = 0.f, xpi = 0.f, xpg = 0.f;
    if (lane == 0) {
        xpf = __ldg(g_xp + HID + j);
        xpi = __ldg(g_xp + 2 * HID + j);
        xpg = __ldg(g_xp + 3 * HID + j);
        xpo = __ldg(g_xp + j);
    }

    for (int t = 0; t < T_STEPS; t++) {
        const unsigned tag = (unsigned)(t + 1);

        // ---- Phase 1a (critical): f, i, g dots -> publish c ----
        float af = 0.f, ai = 0.f, ag = 0.f;
        const float4* wpg = w1v + (size_t)(0 * 8 + w) * 256;
#pragma unroll
        for (int q = 0; q < 8; q++) {
            float4 hv = hreg[q];
            float4 vf = wf[q], vi = wi[q];
            af += vf.x * hv.x + vf.y * hv.y + vf.z * hv.z + vf.w * hv.w;
            ai += vi.x * hv.x + vi.y * hv.y + vi.z * hv.z + vi.w * hv.w;
            float4 vg = wpg[lane + 32 * q];
            ag += vg.x * hv.x + vg.y * hv.y + vg.z * hv.z + vg.w * hv.w;
        }
#pragma unroll
        for (int off = 16; off; off >>= 1) {
            af += __shfl_xor_sync(0xffffffffu, af, off);
            ai += __shfl_xor_sync(0xffffffffu, ai, off);
            ag += __shfl_xor_sync(0xffffffffu, ag, off);
        }
        if (lane == 0) {
            float f_t = fsigmoid(af + xpf + bg1);
            float i_t = fsigmoid(ai + xpi + bg2);
            c_state = f_t * c_state + i_t * ftanh(ag + xpg + bg3);
            publish(g_cpack, j, tag, c_state);   // barrier-1 + data, fused
        }

        // ---- Phase 1b (overlapped with c-exchange): o and W_hr dots ----
        float ao = 0.f, ar = 0.f;
        const float4* wpr = w1v + (size_t)(1 * 8 + w) * 256;
#pragma unroll
        for (int q = 0; q < 8; q++) {
            float4 hv = hreg[q];
            float4 vo = wo[q];
            ao += vo.x * hv.x + vo.y * hv.y + vo.z * hv.z + vo.w * hv.w;
            float4 vr = wpr[lane + 32 * q];
            ar += vr.x * hv.x + vr.y * hv.y + vr.z * hv.z + vr.w * hv.w;
        }
#pragma unroll
        for (int off = 16; off; off >>= 1) {
            ao += __shfl_xor_sync(0xffffffffu, ao, off);
            ar += __shfl_xor_sync(0xffffffffu, ar, off);
        }
        float o_val = 0.f, r1 = 0.f;
        if (lane == 0) {
            o_val = fsigmoid(ao + xpo + bg0);
            r1 = ar;
            // Prefetch x_proj for step t+1 (hidden behind the exchanges)
            if (t + 1 < T_STEPS) {
                const float* xpn = g_xp + (size_t)(t + 1) * GATES;
                xpf = __ldg(xpn + HID + j);
                xpi = __ldg(xpn + 2 * HID + j);
                xpg = __ldg(xpn + 3 * HID + j);
                xpo = __ldg(xpn + j);
            }
        }

        // ---- Gather c_t (grid barrier + data) ----
        poll_gather4(g_cpack, tag, sc, tid, pace, &sink);
        __syncthreads();

        // ---- Phase 2: r2 = c_t . W_cr[:,j] ----
        float a2 = 0.f;
#pragma unroll
        for (int q = 0; q < 8; q++) {
            float4 cv = scv[lane + 32 * q];
            float4 wv = wcr[q];
            a2 += wv.x * cv.x + wv.y * cv.y + wv.z * cv.z + wv.w * cv.w;
        }
#pragma unroll
        for (int off = 16; off; off >>= 1)
            a2 += __shfl_xor_sync(0xffffffffu, a2, off);

        if (lane == 0) {
            float hn = o_val * ftanh(r1 + a2 + brj);
            publish(g_hpack, j, tag, hn);        // publish (critical)
        }

        // ---- Gather h_t; write out coalesced from gathered registers ----
        float4 hv4 = poll_gather4(g_hpack, tag, sh, tid, pace, &sink);
        *(float4*)(out + (size_t)t * HID + 4 * tid) = hv4;
        __syncthreads();
#pragma unroll
        for (int q = 0; q < 8; q++)
            hreg[q] = shv[lane + 32 * q];
    }

    // Prevent sink elimination (never true)
    if (sink == 12345.678f && tid == 9999) out[0] = sink;
}

// ----------------------------------------------------------------------------
// Launch
// ----------------------------------------------------------------------------
extern "C" void kernel_launch(void* const* d_in, const int* in_sizes, int n_in,
                              void* d_out, int out_size) {
    const float* x    = (const float*)d_in[0];   // [4096, 512]
    const float* W_xg = (const float*)d_in[1];   // [512, 4096]
    const float* W_hg = (const float*)d_in[2];   // [1024, 4096]
    const float* b_g  = (const float*)d_in[3];   // [1, 4096]
    const float* W_cr = (const float*)d_in[4];   // [1024, 1024]
    const float* W_hr = (const float*)d_in[5];   // [1024, 1024]
    const float* b_r  = (const float*)d_in[6];   // [1, 1024]
    float* out = (float*)d_out;                  // [4096, 1, 1024]

    (void)in_sizes; (void)n_in; (void)out_size;

    dim3 ggrid(GATES / 128, T_STEPS / 128);
    sgemm_xproj<<<ggrid, 256>>>(x, W_xg);

    cudaFuncSetAttribute(lstm_recur, cudaFuncAttributeMaxDynamicSharedMemorySize,
                         SMEM_BYTES);
    lstm_recur<<<NCTA, NTHREADS, SMEM_BYTES>>>(W_hg, W_hr, W_cr, b_g, b_r, out);
}

// round 14
// speedup vs baseline: 1.0186x; 1.0143x over previous
#include <cuda_runtime.h>
#include <math.h>

// ----------------------------------------------------------------------------
// Problem constants (fixed shapes)
// ----------------------------------------------------------------------------
#define T_STEPS 4096
#define INP_DIM 512
#define HID     1024
#define GATES   4096   // 4*HID

// Recurrent kernel config
#define NCTA      128           // CTAs; each owns 8 hidden columns
#define COLS      8             // columns per CTA
#define NTHREADS  256           // 8 warps; warp w owns column j0+w

// SMEM layout (floats):
#define SW1_F     (2 * 8 * 1024)
#define SCR_F     (8 * 1024)
#define SMEM_FLOATS (SW1_F + SCR_F + 1024 + 1024)
#define SMEM_BYTES  (SMEM_FLOATS * 4)

// Exponential backoff (dependent-FMA units; ~4 cyc each): first poll is
// immediate; failed rounds back off 128->256->512->1024 cyc (cap). The
// critical-path consumer is late and detects on the immediate poll; early
// consumers (long waits, real slack) back off hard, collapsing retry traffic.
#define PACE_MIN 32     // ~128 cyc
#define PACE_MAX 256    // ~1024 cyc

// ----------------------------------------------------------------------------
// Device scratch (allocation-free: __device__ globals)
// ----------------------------------------------------------------------------
__device__ float g_xp[(size_t)T_STEPS * GATES];           // 64 MB: x @ W_xg
__device__ unsigned long long g_cpack[HID];               // (tag<<32)|c bits
__device__ unsigned long long g_hpack[HID];               // (tag<<32)|h bits

// ----------------------------------------------------------------------------
// Kernel 1: x_proj = x @ W_xg   (fp32 SGEMM, 128x128 tile, BK=16, 8x8/thread)
// ----------------------------------------------------------------------------
#define BSP 132   // padded SMEM row

__global__ void __launch_bounds__(256)
sgemm_xproj(const float* __restrict__ A,   // x      [4096, 512]
            const float* __restrict__ B)   // W_xg   [512, 4096]
{
    __shared__ float As[16 * BSP];
    __shared__ float Bs[16 * BSP];

    const int tid = threadIdx.x;
    const int bm  = blockIdx.y;
    const int bn  = blockIdx.x;
    const int ty  = tid >> 4;
    const int tx  = tid & 15;

    float acc[8][8];
#pragma unroll
    for (int i = 0; i < 8; i++)
#pragma unroll
        for (int j = 0; j < 8; j++) acc[i][j] = 0.f;

    for (int kt = 0; kt < INP_DIM / 16; kt++) {
#pragma unroll
        for (int s = 0; s < 2; s++) {
            int f   = tid + s * 256;
            int row = f >> 2;
            int kq  = f & 3;
            float4 av = *(const float4*)(A + (size_t)(bm * 128 + row) * INP_DIM
                                           + kt * 16 + kq * 4);
            As[(kq * 4 + 0) * BSP + row] = av.x;
            As[(kq * 4 + 1) * BSP + row] = av.y;
            As[(kq * 4 + 2) * BSP + row] = av.z;
            As[(kq * 4 + 3) * BSP + row] = av.w;
        }
#pragma unroll
        for (int s = 0; s < 2; s++) {
            int f  = tid + s * 256;
            int kk = f >> 5;
            int cq = f & 31;
            float4 bv = *(const float4*)(B + (size_t)(kt * 16 + kk) * GATES
                                           + bn * 128 + cq * 4);
            *(float4*)(&Bs[kk * BSP + cq * 4]) = bv;
        }
        __syncthreads();

#pragma unroll
        for (int kk = 0; kk < 16; kk++) {
            float4 a0 = *(const float4*)(&As[kk * BSP + ty * 8]);
            float4 a1 = *(const float4*)(&As[kk * BSP + ty * 8 + 4]);
            float4 b0 = *(const float4*)(&Bs[kk * BSP + tx * 8]);
            float4 b1 = *(const float4*)(&Bs[kk * BSP + tx * 8 + 4]);
            float ar[8] = {a0.x, a0.y, a0.z, a0.w, a1.x, a1.y, a1.z, a1.w};
            float br[8] = {b0.x, b0.y, b0.z, b0.w, b1.x, b1.y, b1.z, b1.w};
#pragma unroll
            for (int i = 0; i < 8; i++)
#pragma unroll
                for (int j = 0; j < 8; j++) acc[i][j] += ar[i] * br[j];
        }
        __syncthreads();
    }

#pragma unroll
    for (int i = 0; i < 8; i++) {
        size_t base = (size_t)(bm * 128 + ty * 8 + i) * GATES + bn * 128 + tx * 8;
        *(float4*)(&g_xp[base])     = make_float4(acc[i][0], acc[i][1], acc[i][2], acc[i][3]);
        *(float4*)(&g_xp[base + 4]) = make_float4(acc[i][4], acc[i][5], acc[i][6], acc[i][7]);
    }
}

// ----------------------------------------------------------------------------
// Fast pointwise (fp32, ~1e-6 rel err)
// ----------------------------------------------------------------------------
__device__ __forceinline__ float fsigmoid(float x) {
    return 1.0f / (1.0f + __expf(-x));
}
__device__ __forceinline__ float ftanh(float x) {
    return 1.0f - 2.0f / (__expf(2.0f * x) + 1.0f);
}

// ----------------------------------------------------------------------------
// Tag-stamped broadcast (fused detection+data). Producer: one volatile 8B
// store of (tag<<32)|bits. Consumer: thread tid polls 4 contiguous words
// (one 32B sector) with got-flagged v2.u64 volatile loads; exponential
// backoff between failed rounds.
// ----------------------------------------------------------------------------
__device__ __forceinline__ void publish(unsigned long long* arr, int j,
                                        unsigned tag, float v) {
    unsigned long long p = ((unsigned long long)tag << 32) |
                           (unsigned long long)__float_as_uint(v);
    *((volatile unsigned long long*)(arr + j)) = p;
}

__device__ __forceinline__ void pace_fmas(int n, float* sink) {
    float s = *sink;
    for (int i = 0; i < n; i++)
        asm volatile("fma.rn.f32 %0, %0, %1, %2;"
                     : "+f"(s) : "f"(0.5f), "f"(0.25f));
    *sink = s;
}

// Gathers into dst (smem) AND returns this thread's 4 values
// (used for the coalesced `out` store on the h-exchange).
__device__ __forceinline__ float4 poll_gather4(const unsigned long long* arr,
                                               unsigned tag, float* dst, int tid,
                                               int jitter, float* sink) {
    const unsigned long long* p = arr + 4 * tid;
    unsigned long long a0 = 0, a1 = 0, b0 = 0, b1 = 0;
    bool gotA = false, gotB = false;
    int pace = 0;   // immediate first retry window, then exponential
    for (;;) {
        if (!gotA) {
            asm volatile("ld.volatile.global.v2.u64 {%0,%1},[%2];"
                         : "=l"(a0), "=l"(a1) : "l"(p) : "memory");
        }
        if (!gotB) {
            asm volatile("ld.volatile.global.v2.u64 {%0,%1},[%2];"
                         : "=l"(b0), "=l"(b1) : "l"(p + 2) : "memory");
        }
        gotA = gotA || (((unsigned)(a0 >> 32) == tag) && ((unsigned)(a1 >> 32) == tag));
        gotB = gotB || (((unsigned)(b0 >> 32) == tag) && ((unsigned)(b1 >> 32) == tag));
        if (gotA && gotB) break;
        if (pace) pace_fmas(pace + jitter, sink);
        pace = pace ? ((pace < PACE_MAX) ? (pace << 1) : PACE_MAX) : PACE_MIN;
    }
    float4 v = make_float4(__uint_as_float((unsigned)a0),
                           __uint_as_float((unsigned)a1),
                           __uint_as_float((unsigned)b0),
                           __uint_as_float((unsigned)b1));
    *(float4*)(dst + 4 * tid) = v;
    return v;
}

// ----------------------------------------------------------------------------
// Kernel 2: persistent recurrence. 128 CTAs x 256 threads; warp w owns
// column j = 8*blockIdx.x + w.
// Register-resident: gates o,f,i (W_hg cols) and W_cr column.
// SMEM-resident:     gate g and W_hr column.
// x_proj inputs for step t+1 prefetched during step t.
// ----------------------------------------------------------------------------
__global__ void __launch_bounds__(NTHREADS, 1)
lstm_recur(const float* __restrict__ W_hg,   // [1024, 4096]
           const float* __restrict__ W_hr,   // [1024, 1024]
           const float* __restrict__ W_cr,   // [1024, 1024]
           const float* __restrict__ b_g,    // [4096]
           const float* __restrict__ b_r,    // [1024]
           float* __restrict__ out)          // [4096, 1024]
{
    extern __shared__ float smem[];
    float* sW1     = smem;                    // 2*8*1024 (slot0: g-gate, slot1: W_hr)
    float* scratch = smem + SW1_F;            // 8*1024
    float* sc      = smem + SW1_F + SCR_F;    // 1024
    float* sh      = sc + 1024;               // 1024

    const int tid  = threadIdx.x;
    const int w    = tid >> 5;
    const int lane = tid & 31;
    const int j0   = blockIdx.x * COLS;
    const int j    = j0 + w;

    // Small warp-uniform jitter desmears poll bursts across warps.
    const int jitter = w << 2;   // 0..112 cyc

    // ---- Stage SMEM-resident weights (coalesced) ----
    for (int idx = tid; idx < COLS * 1024; idx += NTHREADS) {
        int cl = idx & 7;
        int k  = idx >> 3;
        sW1[(size_t)(0 * 8 + cl) * 1024 + k] = W_hg[(size_t)k * GATES + 3 * HID + j0 + cl];
        sW1[(size_t)(1 * 8 + cl) * 1024 + k] = W_hr[(size_t)k * HID + j0 + cl];
    }

    // ---- Stage register weights via scratch ----
    // Contract: hreg[q].{x..w} = h[128q + 4*lane + d]
    float4 wo[8], wf[8], wi[8], wcr[8];
    const float4* scrv = (const float4*)scratch;
#pragma unroll
    for (int g = 0; g < 4; g++) {
        __syncthreads();
        for (int idx = tid; idx < COLS * 1024; idx += NTHREADS) {
            int cl = idx & 7;
            int k  = idx >> 3;
            float v;
            if (g < 3) v = W_hg[(size_t)k * GATES + g * HID + j0 + cl];
            else       v = W_cr[(size_t)k * HID + j0 + cl];
            scratch[(size_t)cl * 1024 + k] = v;
        }
        __syncthreads();
#pragma unroll
        for (int q = 0; q < 8; q++) {
            float4 v = scrv[w * 256 + 32 * q + lane];
            if (g == 0) wo[q] = v;
            else if (g == 1) wf[q] = v;
            else if (g == 2) wi[q] = v;
            else wcr[q] = v;
        }
    }
    __syncthreads();

    // Lane-0 constants
    float bg0 = 0.f, bg1 = 0.f, bg2 = 0.f, bg3 = 0.f, brj = 0.f;
    if (lane == 0) {
        bg0 = b_g[j];
        bg1 = b_g[HID + j];
        bg2 = b_g[2 * HID + j];
        bg3 = b_g[3 * HID + j];
        brj = b_r[j];
    }

    float c_state = 0.f;
    float4 hreg[8];
#pragma unroll
    for (int q = 0; q < 8; q++) hreg[q] = make_float4(0.f, 0.f, 0.f, 0.f);

    const float4* w1v = (const float4*)sW1;
    const float4* scv = (const float4*)sc;
    const float4* shv = (const float4*)sh;

    float sink = 1.5f;

    // ---- Prime x_proj pipeline for t=0 ----
    float xpo = 0.f, xpf = 0.f, xpi = 0.f, xpg = 0.f;
    if (lane == 0) {
        xpf = __ldg(g_xp + HID + j);
        xpi = __ldg(g_xp + 2 * HID + j);
        xpg = __ldg(g_xp + 3 * HID + j);
        xpo = __ldg(g_xp + j);
    }

    for (int t = 0; t < T_STEPS; t++) {
        const unsigned tag = (unsigned)(t + 1);

        // ---- Phase 1a (critical): f, i, g dots -> publish c ----
        float af = 0.f, ai = 0.f, ag = 0.f;
        const float4* wpg = w1v + (size_t)(0 * 8 + w) * 256;
#pragma unroll
        for (int q = 0; q < 8; q++) {
            float4 hv = hreg[q];
            float4 vf = wf[q], vi = wi[q];
            af += vf.x * hv.x + vf.y * hv.y + vf.z * hv.z + vf.w * hv.w;
            ai += vi.x * hv.x + vi.y * hv.y + vi.z * hv.z + vi.w * hv.w;
            float4 vg = wpg[lane + 32 * q];
            ag += vg.x * hv.x + vg.y * hv.y + vg.z * hv.z + vg.w * hv.w;
        }
#pragma unroll
        for (int off = 16; off; off >>= 1) {
            af += __shfl_xor_sync(0xffffffffu, af, off);
            ai += __shfl_xor_sync(0xffffffffu, ai, off);
            ag += __shfl_xor_sync(0xffffffffu, ag, off);
        }
        if (lane == 0) {
            float f_t = fsigmoid(af + xpf + bg1);
            float i_t = fsigmoid(ai + xpi + bg2);
            c_state = f_t * c_state + i_t * ftanh(ag + xpg + bg3);
            publish(g_cpack, j, tag, c_state);   // barrier-1 + data, fused
        }

        // ---- Phase 1b (overlapped with c-exchange): o and W_hr dots ----
        float ao = 0.f, ar = 0.f;
        const float4* wpr = w1v + (size_t)(1 * 8 + w) * 256;
#pragma unroll
        for (int q = 0; q < 8; q++) {
            float4 hv = hreg[q];
            float4 vo = wo[q];
            ao += vo.x * hv.x + vo.y * hv.y + vo.z * hv.z + vo.w * hv.w;
            float4 vr = wpr[lane + 32 * q];
            ar += vr.x * hv.x + vr.y * hv.y + vr.z * hv.z + vr.w * hv.w;
        }
#pragma unroll
        for (int off = 16; off; off >>= 1) {
            ao += __shfl_xor_sync(0xffffffffu, ao, off);
            ar += __shfl_xor_sync(0xffffffffu, ar, off);
        }
        float o_val = 0.f, r1 = 0.f;
        if (lane == 0) {
            o_val = fsigmoid(ao + xpo + bg0);
            r1 = ar;
            // Prefetch x_proj for step t+1 (hidden behind the exchanges)
            if (t + 1 < T_STEPS) {
                const float* xpn = g_xp + (size_t)(t + 1) * GATES;
                xpf = __ldg(xpn + HID + j);
                xpi = __ldg(xpn + 2 * HID + j);
                xpg = __ldg(xpn + 3 * HID + j);
                xpo = __ldg(xpn + j);
            }
        }

        // ---- Gather c_t (grid barrier + data) ----
        poll_gather4(g_cpack, tag, sc, tid, jitter, &sink);
        __syncthreads();

        // ---- Phase 2: r2 = c_t . W_cr[:,j] ----
        float a2 = 0.f;
#pragma unroll
        for (int q = 0; q < 8; q++) {
            float4 cv = scv[lane + 32 * q];
            float4 wv = wcr[q];
            a2 += wv.x * cv.x + wv.y * cv.y + wv.z * cv.z + wv.w * cv.w;
        }
#pragma unroll
        for (int off = 16; off; off >>= 1)
            a2 += __shfl_xor_sync(0xffffffffu, a2, off);

        if (lane == 0) {
            float hn = o_val * ftanh(r1 + a2 + brj);
            publish(g_hpack, j, tag, hn);        // publish (critical)
        }

        // ---- Gather h_t; write out coalesced from gathered registers ----
        float4 hv4 = poll_gather4(g_hpack, tag, sh, tid, jitter, &sink);
        *(float4*)(out + (size_t)t * HID + 4 * tid) = hv4;
        __syncthreads();
#pragma unroll
        for (int q = 0; q < 8; q++)
            hreg[q] = shv[lane + 32 * q];
    }

    // Prevent sink elimination (never true)
    if (sink == 12345.678f && tid == 9999) out[0] = sink;
}

// ----------------------------------------------------------------------------
// Launch
// ----------------------------------------------------------------------------
extern "C" void kernel_launch(void* const* d_in, const int* in_sizes, int n_in,
                              void* d_out, int out_size) {
    const float* x    = (const float*)d_in[0];   // [4096, 512]
    const float* W_xg = (const float*)d_in[1];   // [512, 4096]
    const float* W_hg = (const float*)d_in[2];   // [1024, 4096]
    const float* b_g  = (const float*)d_in[3];   // [1, 4096]
    const float* W_cr = (const float*)d_in[4];   // [1024, 1024]
    const float* W_hr = (const float*)d_in[5];   // [1024, 1024]
    const float* b_r  = (const float*)d_in[6];   // [1, 1024]
    float* out = (float*)d_out;                  // [4096, 1, 1024]

    (void)in_sizes; (void)n_in; (void)out_size;

    dim3 ggrid(GATES / 128, T_STEPS / 128);
    sgemm_xproj<<<ggrid, 256>>>(x, W_xg);

    cudaFuncSetAttribute(lstm_recur, cudaFuncAttributeMaxDynamicSharedMemorySize,
                         SMEM_BYTES);
    lstm_recur<<<NCTA, NTHREADS, SMEM_BYTES>>>(W_hg, W_hr, W_cr, b_g, b_r, out);
}

// round 15
// speedup vs baseline: 1.1025x; 1.0825x over previous
#include <cuda_runtime.h>
#include <math.h>

// ----------------------------------------------------------------------------
// Problem constants (fixed shapes)
// ----------------------------------------------------------------------------
#define T_STEPS 4096
#define INP_DIM 512
#define HID     1024
#define GATES   4096   // 4*HID

// Recurrent kernel config
#define NCTA      128           // CTAs; each owns 8 hidden columns
#define COLS      8             // columns per CTA
#define NTHREADS  256           // 8 warps; warp w owns column j0+w

// SMEM layout (floats):
#define SW1_F     (2 * 8 * 1024)
#define SCR_F     (8 * 1024)
#define SMEM_FLOATS (SW1_F + SCR_F + 1024 + 1024)
#define SMEM_BYTES  (SMEM_FLOATS * 4)

// Poll pacing (dependent-FMA units; ~4 cyc each)
#define PACE_STEADY 44   // ~176 cyc (best-measured family); traffic now halved

// ----------------------------------------------------------------------------
// Device scratch (allocation-free: __device__ globals)
// ----------------------------------------------------------------------------
__device__ float g_xp[(size_t)T_STEPS * GATES];   // 64 MB: x @ W_xg
// Exchange arrays: fp32 values with the step-parity tag packed into mantissa
// bit 0. The gather is a full barrier => no CTA leads by more than one step,
// so a 1-bit tag distinguishes fresh from stale. Zero-init state has bit0=0;
// tag (t+1)&1 = 1 at t=0 avoids colliding with it.
__device__ unsigned g_cpack[HID];
__device__ unsigned g_hpack[HID];

// ----------------------------------------------------------------------------
// Kernel 1: x_proj = x @ W_xg   (fp32 SGEMM, 128x128 tile, BK=16, 8x8/thread)
// ----------------------------------------------------------------------------
#define BSP 132   // padded SMEM row

__global__ void __launch_bounds__(256)
sgemm_xproj(const float* __restrict__ A,   // x      [4096, 512]
            const float* __restrict__ B)   // W_xg   [512, 4096]
{
    __shared__ float As[16 * BSP];
    __shared__ float Bs[16 * BSP];

    const int tid = threadIdx.x;
    const int bm  = blockIdx.y;
    const int bn  = blockIdx.x;
    const int ty  = tid >> 4;
    const int tx  = tid & 15;

    float acc[8][8];
#pragma unroll
    for (int i = 0; i < 8; i++)
#pragma unroll
        for (int j = 0; j < 8; j++) acc[i][j] = 0.f;

    for (int kt = 0; kt < INP_DIM / 16; kt++) {
#pragma unroll
        for (int s = 0; s < 2; s++) {
            int f   = tid + s * 256;
            int row = f >> 2;
            int kq  = f & 3;
            float4 av = *(const float4*)(A + (size_t)(bm * 128 + row) * INP_DIM
                                           + kt * 16 + kq * 4);
            As[(kq * 4 + 0) * BSP + row] = av.x;
            As[(kq * 4 + 1) * BSP + row] = av.y;
            As[(kq * 4 + 2) * BSP + row] = av.z;
            As[(kq * 4 + 3) * BSP + row] = av.w;
        }
#pragma unroll
        for (int s = 0; s < 2; s++) {
            int f  = tid + s * 256;
            int kk = f >> 5;
            int cq = f & 31;
            float4 bv = *(const float4*)(B + (size_t)(kt * 16 + kk) * GATES
                                           + bn * 128 + cq * 4);
            *(float4*)(&Bs[kk * BSP + cq * 4]) = bv;
        }
        __syncthreads();

#pragma unroll
        for (int kk = 0; kk < 16; kk++) {
            float4 a0 = *(const float4*)(&As[kk * BSP + ty * 8]);
            float4 a1 = *(const float4*)(&As[kk * BSP + ty * 8 + 4]);
            float4 b0 = *(const float4*)(&Bs[kk * BSP + tx * 8]);
            float4 b1 = *(const float4*)(&Bs[kk * BSP + tx * 8 + 4]);
            float ar[8] = {a0.x, a0.y, a0.z, a0.w, a1.x, a1.y, a1.z, a1.w};
            float br[8] = {b0.x, b0.y, b0.z, b0.w, b1.x, b1.y, b1.z, b1.w};
#pragma unroll
            for (int i = 0; i < 8; i++)
#pragma unroll
                for (int j = 0; j < 8; j++) acc[i][j] += ar[i] * br[j];
        }
        __syncthreads();
    }

#pragma unroll
    for (int i = 0; i < 8; i++) {
        size_t base = (size_t)(bm * 128 + ty * 8 + i) * GATES + bn * 128 + tx * 8;
        *(float4*)(&g_xp[base])     = make_float4(acc[i][0], acc[i][1], acc[i][2], acc[i][3]);
        *(float4*)(&g_xp[base + 4]) = make_float4(acc[i][4], acc[i][5], acc[i][6], acc[i][7]);
    }
}

// ----------------------------------------------------------------------------
// Fast pointwise (fp32, ~1e-6 rel err)
// ----------------------------------------------------------------------------
__device__ __forceinline__ float fsigmoid(float x) {
    return 1.0f / (1.0f + __expf(-x));
}
__device__ __forceinline__ float ftanh(float x) {
    return 1.0f - 2.0f / (__expf(2.0f * x) + 1.0f);
}

// ----------------------------------------------------------------------------
// Mantissa-tagged broadcast. Producer: one volatile 4B store of the fp32
// value with mantissa bit0 = (t+1)&1 (rel. perturbation 2^-24). Consumer:
// thread tid polls its 4 contiguous columns with ONE ld.volatile.v4.u32
// (16B, single 32B sector) until all four tag bits match.
// ----------------------------------------------------------------------------
__device__ __forceinline__ void publish(unsigned* arr, int j,
                                        unsigned tagbit, float v) {
    unsigned b = (__float_as_uint(v) & ~1u) | tagbit;
    *((volatile unsigned*)(arr + j)) = b;
}

__device__ __forceinline__ void pace_fmas(int n, float* sink) {
    float s = *sink;
    for (int i = 0; i < n; i++)
        asm volatile("fma.rn.f32 %0, %0, %1, %2;"
                     : "+f"(s) : "f"(0.5f), "f"(0.25f));
    *sink = s;
}

// Gathers into dst (smem) AND returns this thread's 4 values
// (used for the coalesced `out` store on the h-exchange).
__device__ __forceinline__ float4 poll_gather4(const unsigned* arr,
                                               unsigned tagbit, float* dst,
                                               int tid, int pace, float* sink) {
    const unsigned* p = arr + 4 * tid;
    unsigned x, y, z, u;
    for (;;) {
        asm volatile("ld.volatile.global.v4.u32 {%0,%1,%2,%3},[%4];"
                     : "=r"(x), "=r"(y), "=r"(z), "=r"(u) : "l"(p) : "memory");
        unsigned m = tagbit ? (x & y & z & u) : ~(x | y | z | u);
        if (m & 1u) break;
        pace_fmas(pace, sink);
    }
    float4 v = make_float4(__uint_as_float(x), __uint_as_float(y),
                           __uint_as_float(z), __uint_as_float(u));
    *(float4*)(dst + 4 * tid) = v;
    return v;
}

// ----------------------------------------------------------------------------
// Kernel 2: persistent recurrence. 128 CTAs x 256 threads; warp w owns
// column j = 8*blockIdx.x + w.
// Register-resident: gates o,f,i (W_hg cols) and W_cr column.
// SMEM-resident:     gate g and W_hr column.
// x_proj inputs for step t+1 prefetched during step t.
// ----------------------------------------------------------------------------
__global__ void __launch_bounds__(NTHREADS, 1)
lstm_recur(const float* __restrict__ W_hg,   // [1024, 4096]
           const float* __restrict__ W_hr,   // [1024, 1024]
           const float* __restrict__ W_cr,   // [1024, 1024]
           const float* __restrict__ b_g,    // [4096]
           const float* __restrict__ b_r,    // [1024]
           float* __restrict__ out)          // [4096, 1024]
{
    extern __shared__ float smem[];
    float* sW1     = smem;                    // 2*8*1024 (slot0: g-gate, slot1: W_hr)
    float* scratch = smem + SW1_F;            // 8*1024
    float* sc      = smem + SW1_F + SCR_F;    // 1024
    float* sh      = sc + 1024;               // 1024

    const int tid  = threadIdx.x;
    const int w    = tid >> 5;
    const int lane = tid & 31;
    const int j0   = blockIdx.x * COLS;
    const int j    = j0 + w;

    // Per-warp pace jitter (warp-uniform) desmears poll bursts.
    const int pace = PACE_STEADY + (w << 2);   // 176..288 cyc

    // ---- Stage SMEM-resident weights (coalesced) ----
    for (int idx = tid; idx < COLS * 1024; idx += NTHREADS) {
        int cl = idx & 7;
        int k  = idx >> 3;
        sW1[(size_t)(0 * 8 + cl) * 1024 + k] = W_hg[(size_t)k * GATES + 3 * HID + j0 + cl];
        sW1[(size_t)(1 * 8 + cl) * 1024 + k] = W_hr[(size_t)k * HID + j0 + cl];
    }

    // ---- Stage register weights via scratch ----
    // Contract: hreg[q].{x..w} = h[128q + 4*lane + d]
    float4 wo[8], wf[8], wi[8], wcr[8];
    const float4* scrv = (const float4*)scratch;
#pragma unroll
    for (int g = 0; g < 4; g++) {
        __syncthreads();
        for (int idx = tid; idx < COLS * 1024; idx += NTHREADS) {
            int cl = idx & 7;
            int k  = idx >> 3;
            float v;
            if (g < 3) v = W_hg[(size_t)k * GATES + g * HID + j0 + cl];
            else       v = W_cr[(size_t)k * HID + j0 + cl];
            scratch[(size_t)cl * 1024 + k] = v;
        }
        __syncthreads();
#pragma unroll
        for (int q = 0; q < 8; q++) {
            float4 v = scrv[w * 256 + 32 * q + lane];
            if (g == 0) wo[q] = v;
            else if (g == 1) wf[q] = v;
            else if (g == 2) wi[q] = v;
            else wcr[q] = v;
        }
    }
    __syncthreads();

    // Lane-0 constants
    float bg0 = 0.f, bg1 = 0.f, bg2 = 0.f, bg3 = 0.f, brj = 0.f;
    if (lane == 0) {
        bg0 = b_g[j];
        bg1 = b_g[HID + j];
        bg2 = b_g[2 * HID + j];
        bg3 = b_g[3 * HID + j];
        brj = b_r[j];
    }

    float c_state = 0.f;
    float4 hreg[8];
#pragma unroll
    for (int q = 0; q < 8; q++) hreg[q] = make_float4(0.f, 0.f, 0.f, 0.f);

    const float4* w1v = (const float4*)sW1;
    const float4* scv = (const float4*)sc;
    const float4* shv = (const float4*)sh;

    float sink = 1.5f;

    // ---- Prime x_proj pipeline for t=0 ----
    float xpo = 0.f, xpf = 0.f, xpi = 0.f, xpg = 0.f;
    if (lane == 0) {
        xpf = __ldg(g_xp + HID + j);
        xpi = __ldg(g_xp + 2 * HID + j);
        xpg = __ldg(g_xp + 3 * HID + j);
        xpo = __ldg(g_xp + j);
    }

    for (int t = 0; t < T_STEPS; t++) {
        const unsigned tagbit = (unsigned)((t + 1) & 1);

        // ---- Phase 1a (critical): f, i, g dots -> publish c ----
        float af = 0.f, ai = 0.f, ag = 0.f;
        const float4* wpg = w1v + (size_t)(0 * 8 + w) * 256;
#pragma unroll
        for (int q = 0; q < 8; q++) {
            float4 hv = hreg[q];
            float4 vf = wf[q], vi = wi[q];
            af += vf.x * hv.x + vf.y * hv.y + vf.z * hv.z + vf.w * hv.w;
            ai += vi.x * hv.x + vi.y * hv.y + vi.z * hv.z + vi.w * hv.w;
            float4 vg = wpg[lane + 32 * q];
            ag += vg.x * hv.x + vg.y * hv.y + vg.z * hv.z + vg.w * hv.w;
        }
#pragma unroll
        for (int off = 16; off; off >>= 1) {
            af += __shfl_xor_sync(0xffffffffu, af, off);
            ai += __shfl_xor_sync(0xffffffffu, ai, off);
            ag += __shfl_xor_sync(0xffffffffu, ag, off);
        }
        if (lane == 0) {
            float f_t = fsigmoid(af + xpf + bg1);
            float i_t = fsigmoid(ai + xpi + bg2);
            c_state = f_t * c_state + i_t * ftanh(ag + xpg + bg3);
            publish(g_cpack, j, tagbit, c_state);   // barrier-1 + data, fused
        }

        // ---- Phase 1b (overlapped with c-exchange): o and W_hr dots ----
        float ao = 0.f, ar = 0.f;
        const float4* wpr = w1v + (size_t)(1 * 8 + w) * 256;
#pragma unroll
        for (int q = 0; q < 8; q++) {
            float4 hv = hreg[q];
            float4 vo = wo[q];
            ao += vo.x * hv.x + vo.y * hv.y + vo.z * hv.z + vo.w * hv.w;
            float4 vr = wpr[lane + 32 * q];
            ar += vr.x * hv.x + vr.y * hv.y + vr.z * hv.z + vr.w * hv.w;
        }
#pragma unroll
        for (int off = 16; off; off >>= 1) {
            ao += __shfl_xor_sync(0xffffffffu, ao, off);
            ar += __shfl_xor_sync(0xffffffffu, ar, off);
        }
        float o_val = 0.f, r1 = 0.f;
        if (lane == 0) {
            o_val = fsigmoid(ao + xpo + bg0);
            r1 = ar;
            // Prefetch x_proj for step t+1 (hidden behind the exchanges)
            if (t + 1 < T_STEPS) {
                const float* xpn = g_xp + (size_t)(t + 1) * GATES;
                xpf = __ldg(xpn + HID + j);
                xpi = __ldg(xpn + 2 * HID + j);
                xpg = __ldg(xpn + 3 * HID + j);
                xpo = __ldg(xpn + j);
            }
        }

        // ---- Gather c_t (grid barrier + data) ----
        poll_gather4(g_cpack, tagbit, sc, tid, pace, &sink);
        __syncthreads();

        // ---- Phase 2: r2 = c_t . W_cr[:,j] ----
        float a2 = 0.f;
#pragma unroll
        for (int q = 0; q < 8; q++) {
            float4 cv = scv[lane + 32 * q];
            float4 wv = wcr[q];
            a2 += wv.x * cv.x + wv.y * cv.y + wv.z * cv.z + wv.w * cv.w;
        }
#pragma unroll
        for (int off = 16; off; off >>= 1)
            a2 += __shfl_xor_sync(0xffffffffu, a2, off);

        if (lane == 0) {
            float hn = o_val * ftanh(r1 + a2 + brj);
            publish(g_hpack, j, tagbit, hn);        // publish (critical)
        }

        // ---- Gather h_t; write out coalesced from gathered registers ----
        float4 hv4 = poll_gather4(g_hpack, tagbit, sh, tid, pace, &sink);
        *(float4*)(out + (size_t)t * HID + 4 * tid) = hv4;
        __syncthreads();
#pragma unroll
        for (int q = 0; q < 8; q++)
            hreg[q] = shv[lane + 32 * q];
    }

    // Prevent sink elimination (never true)
    if (sink == 12345.678f && tid == 9999) out[0] = sink;
}

// ----------------------------------------------------------------------------
// Launch
// ----------------------------------------------------------------------------
extern "C" void kernel_launch(void* const* d_in, const int* in_sizes, int n_in,
                              void* d_out, int out_size) {
    const float* x    = (const float*)d_in[0];   // [4096, 512]
    const float* W_xg = (const float*)d_in[1];   // [512, 4096]
    const float* W_hg = (const float*)d_in[2];   // [1024, 4096]
    const float* b_g  = (const float*)d_in[3];   // [1, 4096]
    const float* W_cr = (const float*)d_in[4];   // [1024, 1024]
    const float* W_hr = (const float*)d_in[5];   // [1024, 1024]
    const float* b_r  = (const float*)d_in[6];   // [1, 1024]
    float* out = (float*)d_out;                  // [4096, 1, 1024]

    (void)in_sizes; (void)n_in; (void)out_size;

    dim3 ggrid(GATES / 128, T_STEPS / 128);
    sgemm_xproj<<<ggrid, 256>>>(x, W_xg);

    cudaFuncSetAttribute(lstm_recur, cudaFuncAttributeMaxDynamicSharedMemorySize,
                         SMEM_BYTES);
    lstm_recur<<<NCTA, NTHREADS, SMEM_BYTES>>>(W_hg, W_hr, W_cr, b_g, b_r, out);
}